// round 1
// baseline (speedup 1.0000x reference)
#include <cuda_runtime.h>
#include <math.h>

// Problem constants
#define kB 2
#define kS 2048
#define kE 1024
#define kH 16
#define kD 64
#define kBH (kB * kH)
#define kScale 0.125f

// Scratch (device globals: allocation-free)
static __device__ float g_q[kBH * kS * kD];
static __device__ float g_k[kBH * kS * kD];
static __device__ float g_v[kBH * kS * kD];
static __device__ float g_ctx[kB * kS * kE];

// ---------------- f32x2 packed helpers ----------------
__device__ __forceinline__ unsigned long long pk2(float lo, float hi) {
    unsigned long long r;
    asm("mov.b64 %0, {%1, %2};" : "=l"(r) : "f"(lo), "f"(hi));
    return r;
}
__device__ __forceinline__ float2 up2(unsigned long long v) {
    float2 r;
    asm("mov.b64 {%0, %1}, %2;" : "=f"(r.x), "=f"(r.y) : "l"(v));
    return r;
}
__device__ __forceinline__ void fma2(unsigned long long& d, unsigned long long a,
                                     unsigned long long b) {
    asm("fma.rn.f32x2 %0, %1, %2, %0;" : "+l"(d) : "l"(a), "l"(b));
}
__device__ __forceinline__ void mul2(unsigned long long& d, unsigned long long a) {
    asm("mul.rn.f32x2 %0, %0, %1;" : "+l"(d) : "l"(a));
}

// ---------------- GEMM 1: qkv = query @ w_qkv^T, scattered to head layout ----------------
// A: [4096, 1024] row-major (query), W: [3072, 1024] row-major (w_qkv)
// out[m, n] = sum_k A[m,k] * W[n,k] ; scattered to g_q/g_k/g_v as [b*H+h][s][d]
__global__ __launch_bounds__(256) void gemm_qkv_kernel(const float* __restrict__ A,
                                                       const float* __restrict__ W) {
    __shared__ float As[16][132];
    __shared__ float Ws[16][68];
    const int t = threadIdx.x;
    const int m0 = blockIdx.x * 128;
    const int n0 = blockIdx.y * 64;
    const int ar = t >> 1, ak = (t & 1) * 8;
    const int wr = t >> 2, wk = (t & 3) * 4;
    const float* Ap = A + (size_t)(m0 + ar) * kE + ak;
    const float* Wp = W + (size_t)(n0 + wr) * kE + wk;
    const int tm = (t & 15) * 8;
    const int tn = (t >> 4) * 4;

    unsigned long long acc[4][4];
#pragma unroll
    for (int i = 0; i < 4; i++)
#pragma unroll
        for (int j = 0; j < 4; j++) acc[i][j] = 0ull;

    float4 a0 = *(const float4*)Ap;
    float4 a1 = *(const float4*)(Ap + 4);
    float4 w0 = *(const float4*)Wp;

    for (int k0 = 0; k0 < kE; k0 += 16) {
        __syncthreads();
        As[ak + 0][ar] = a0.x; As[ak + 1][ar] = a0.y;
        As[ak + 2][ar] = a0.z; As[ak + 3][ar] = a0.w;
        As[ak + 4][ar] = a1.x; As[ak + 5][ar] = a1.y;
        As[ak + 6][ar] = a1.z; As[ak + 7][ar] = a1.w;
        Ws[wk + 0][wr] = w0.x; Ws[wk + 1][wr] = w0.y;
        Ws[wk + 2][wr] = w0.z; Ws[wk + 3][wr] = w0.w;
        __syncthreads();
        if (k0 + 16 < kE) {
            Ap += 16; Wp += 16;
            a0 = *(const float4*)Ap;
            a1 = *(const float4*)(Ap + 4);
            w0 = *(const float4*)Wp;
        }
#pragma unroll
        for (int kk = 0; kk < 16; kk++) {
            const ulonglong2* arow = (const ulonglong2*)&As[kk][tm];
            ulonglong2 aa = arow[0];
            ulonglong2 ab = arow[1];
            float4 wv = *(const float4*)&Ws[kk][tn];
            unsigned long long b0 = pk2(wv.x, wv.x), b1 = pk2(wv.y, wv.y),
                               b2 = pk2(wv.z, wv.z), b3 = pk2(wv.w, wv.w);
            fma2(acc[0][0], aa.x, b0); fma2(acc[0][1], aa.x, b1);
            fma2(acc[0][2], aa.x, b2); fma2(acc[0][3], aa.x, b3);
            fma2(acc[1][0], aa.y, b0); fma2(acc[1][1], aa.y, b1);
            fma2(acc[1][2], aa.y, b2); fma2(acc[1][3], aa.y, b3);
            fma2(acc[2][0], ab.x, b0); fma2(acc[2][1], ab.x, b1);
            fma2(acc[2][2], ab.x, b2); fma2(acc[2][3], ab.x, b3);
            fma2(acc[3][0], ab.y, b0); fma2(acc[3][1], ab.y, b1);
            fma2(acc[3][2], ab.y, b2); fma2(acc[3][3], ab.y, b3);
        }
    }
    // scatter epilogue: n0 is 64-aligned so (which, h) fixed per block; d = tn + j
    const int which = n0 >> 10;
    const int h = (n0 & 1023) >> 6;
    float* dst = which == 0 ? g_q : (which == 1 ? g_k : g_v);
#pragma unroll
    for (int mi = 0; mi < 4; mi++) {
        float2 c0 = up2(acc[mi][0]), c1 = up2(acc[mi][1]);
        float2 c2 = up2(acc[mi][2]), c3 = up2(acc[mi][3]);
        int m = m0 + tm + 2 * mi;
        int bb = m >> 11, s = m & (kS - 1);
        size_t base = (((size_t)(bb * kH + h)) * kS + s) * kD + tn;
        *(float4*)&dst[base] = make_float4(c0.x, c1.x, c2.x, c3.x);
        *(float4*)&dst[base + kD] = make_float4(c0.y, c1.y, c2.y, c3.y);
    }
}

// ---------------- GEMM 2: out = ctx @ w_out^T ----------------
__global__ __launch_bounds__(256) void gemm_out_kernel(const float* __restrict__ W,
                                                       float* __restrict__ out) {
    const float* A = g_ctx;
    __shared__ float As[16][132];
    __shared__ float Ws[16][68];
    const int t = threadIdx.x;
    const int m0 = blockIdx.x * 128;
    const int n0 = blockIdx.y * 64;
    const int ar = t >> 1, ak = (t & 1) * 8;
    const int wr = t >> 2, wk = (t & 3) * 4;
    const float* Ap = A + (size_t)(m0 + ar) * kE + ak;
    const float* Wp = W + (size_t)(n0 + wr) * kE + wk;
    const int tm = (t & 15) * 8;
    const int tn = (t >> 4) * 4;

    unsigned long long acc[4][4];
#pragma unroll
    for (int i = 0; i < 4; i++)
#pragma unroll
        for (int j = 0; j < 4; j++) acc[i][j] = 0ull;

    float4 a0 = *(const float4*)Ap;
    float4 a1 = *(const float4*)(Ap + 4);
    float4 w0 = *(const float4*)Wp;

    for (int k0 = 0; k0 < kE; k0 += 16) {
        __syncthreads();
        As[ak + 0][ar] = a0.x; As[ak + 1][ar] = a0.y;
        As[ak + 2][ar] = a0.z; As[ak + 3][ar] = a0.w;
        As[ak + 4][ar] = a1.x; As[ak + 5][ar] = a1.y;
        As[ak + 6][ar] = a1.z; As[ak + 7][ar] = a1.w;
        Ws[wk + 0][wr] = w0.x; Ws[wk + 1][wr] = w0.y;
        Ws[wk + 2][wr] = w0.z; Ws[wk + 3][wr] = w0.w;
        __syncthreads();
        if (k0 + 16 < kE) {
            Ap += 16; Wp += 16;
            a0 = *(const float4*)Ap;
            a1 = *(const float4*)(Ap + 4);
            w0 = *(const float4*)Wp;
        }
#pragma unroll
        for (int kk = 0; kk < 16; kk++) {
            const ulonglong2* arow = (const ulonglong2*)&As[kk][tm];
            ulonglong2 aa = arow[0];
            ulonglong2 ab = arow[1];
            float4 wv = *(const float4*)&Ws[kk][tn];
            unsigned long long b0 = pk2(wv.x, wv.x), b1 = pk2(wv.y, wv.y),
                               b2 = pk2(wv.z, wv.z), b3 = pk2(wv.w, wv.w);
            fma2(acc[0][0], aa.x, b0); fma2(acc[0][1], aa.x, b1);
            fma2(acc[0][2], aa.x, b2); fma2(acc[0][3], aa.x, b3);
            fma2(acc[1][0], aa.y, b0); fma2(acc[1][1], aa.y, b1);
            fma2(acc[1][2], aa.y, b2); fma2(acc[1][3], aa.y, b3);
            fma2(acc[2][0], ab.x, b0); fma2(acc[2][1], ab.x, b1);
            fma2(acc[2][2], ab.x, b2); fma2(acc[2][3], ab.x, b3);
            fma2(acc[3][0], ab.y, b0); fma2(acc[3][1], ab.y, b1);
            fma2(acc[3][2], ab.y, b2); fma2(acc[3][3], ab.y, b3);
        }
    }
#pragma unroll
    for (int mi = 0; mi < 4; mi++) {
        float2 c0 = up2(acc[mi][0]), c1 = up2(acc[mi][1]);
        float2 c2 = up2(acc[mi][2]), c3 = up2(acc[mi][3]);
        int m = m0 + tm + 2 * mi;
        size_t base = (size_t)m * kE + n0 + tn;
        *(float4*)&out[base] = make_float4(c0.x, c1.x, c2.x, c3.x);
        *(float4*)&out[base + kE] = make_float4(c0.y, c1.y, c2.y, c3.y);
    }
}

// ---------------- RoPE (+ fold SCALE into q) ----------------
__global__ void rope_kernel() {
    int idx = blockIdx.x * 256 + threadIdx.x;  // exactly 32*2048*32 threads
    int i = idx & 31;
    int s = (idx >> 5) & (kS - 1);
    int bh = idx >> 16;
    size_t base = ((size_t)bh * kS + s) * kD + 2 * i;
    // inv_freq = 10000^(-2i/64) = exp(-i * ln(10000)/32)
    float inv = expf(-(float)i * (9.210340371976184f / 32.0f));
    float freq = (float)s * inv;
    float sn, cs;
    sincosf(freq, &sn, &cs);
    float2 q2 = *(float2*)&g_q[base];
    float2 k2 = *(float2*)&g_k[base];
    float qr = (q2.x * cs - q2.y * sn) * kScale;
    float qi = (q2.x * sn + q2.y * cs) * kScale;
    *(float2*)&g_q[base] = make_float2(qr, qi);
    float kr = k2.x * cs - k2.y * sn;
    float ki = k2.x * sn + k2.y * cs;
    *(float2*)&g_k[base] = make_float2(kr, ki);
}

// ---------------- Flash attention (fp32, f32x2 packed FMA) ----------------
// grid: (32 q-tiles, 32 bh). block: 256 threads.
// Thread layout: quad per query row (r = t>>2, g = t&3, 16 d/cols per lane).
__global__ __launch_bounds__(256) void attn_kernel() {
    __shared__ float kT[64 * 68];  // d-major: kT[d*68 + c]
    __shared__ float vs[64 * 68];  // row-major: vs[j*68 + d]
    const int t = threadIdx.x;
    const int lane = t & 31;
    const int r = t >> 2;
    const int g = t & 3;
    const int d0 = g * 16;
    const int bh = blockIdx.y;
    const int q0 = blockIdx.x * 64;
    const float* qb = g_q + (size_t)bh * kS * kD;
    const float* kb = g_k + (size_t)bh * kS * kD;
    const float* vb = g_v + (size_t)bh * kS * kD;

    // q row chunk in registers
    float qreg[16];
    {
        const float* src = qb + (size_t)(q0 + r) * kD + d0;
#pragma unroll
        for (int i = 0; i < 4; i++) {
            float4 v4 = *(const float4*)(src + 4 * i);
            qreg[4 * i + 0] = v4.x; qreg[4 * i + 1] = v4.y;
            qreg[4 * i + 2] = v4.z; qreg[4 * i + 3] = v4.w;
        }
    }

    float m_i = -1e30f, l_i = 0.f;
    unsigned long long o2[8];
#pragma unroll
    for (int i = 0; i < 8; i++) o2[i] = 0ull;

    for (int kt = 0; kt < 32; kt++) {
        __syncthreads();  // protect kT/vs from previous tile's readers
        {
            const float* ksrc = kb + (size_t)(kt * 64 + r) * kD + d0;
            const float* vsrc = vb + (size_t)(kt * 64 + r) * kD + d0;
#pragma unroll
            for (int i = 0; i < 4; i++) {
                float4 kv = *(const float4*)(ksrc + 4 * i);
                kT[(d0 + 4 * i + 0) * 68 + r] = kv.x;
                kT[(d0 + 4 * i + 1) * 68 + r] = kv.y;
                kT[(d0 + 4 * i + 2) * 68 + r] = kv.z;
                kT[(d0 + 4 * i + 3) * 68 + r] = kv.w;
                *(float4*)&vs[r * 68 + d0 + 4 * i] = *(const float4*)(vsrc + 4 * i);
            }
        }
        __syncthreads();

        // scores: sc[c] = sum_d q[r][d] * k[c][d], c = d0..d0+15, packed pairs
        unsigned long long sc2[8];
#pragma unroll
        for (int j = 0; j < 8; j++) sc2[j] = 0ull;
#pragma unroll 1
        for (int gs = 0; gs < 4; gs++) {
            const int qsrc = (lane & ~3) | gs;
#pragma unroll
            for (int dd = 0; dd < 16; dd++) {
                float qv = __shfl_sync(0xffffffffu, qreg[dd], qsrc);
                unsigned long long q2 = pk2(qv, qv);
                const ulonglong2* kr4 =
                    (const ulonglong2*)&kT[(gs * 16 + dd) * 68 + d0];
                ulonglong2 ka = kr4[0], kb2 = kr4[1];
                fma2(sc2[0], q2, ka.x);  fma2(sc2[1], q2, ka.y);
                fma2(sc2[2], q2, kb2.x); fma2(sc2[3], q2, kb2.y);
                ulonglong2 kc = kr4[2], kd2 = kr4[3];
                fma2(sc2[4], q2, kc.x);  fma2(sc2[5], q2, kc.y);
                fma2(sc2[6], q2, kd2.x); fma2(sc2[7], q2, kd2.y);
            }
        }

        // online softmax (quad-wide row reduction via shuffles)
        float p[16];
        float m_t = -1e30f;
#pragma unroll
        for (int j = 0; j < 8; j++) {
            float2 v = up2(sc2[j]);
            p[2 * j] = v.x; p[2 * j + 1] = v.y;
            m_t = fmaxf(m_t, fmaxf(v.x, v.y));
        }
        m_t = fmaxf(m_t, __shfl_xor_sync(0xffffffffu, m_t, 1));
        m_t = fmaxf(m_t, __shfl_xor_sync(0xffffffffu, m_t, 2));
        float m_new = fmaxf(m_i, m_t);
        float corr = __expf(m_i - m_new);
        float rs = 0.f;
#pragma unroll
        for (int j = 0; j < 16; j++) {
            p[j] = __expf(p[j] - m_new);
            rs += p[j];
        }
        rs += __shfl_xor_sync(0xffffffffu, rs, 1);
        rs += __shfl_xor_sync(0xffffffffu, rs, 2);
        l_i = l_i * corr + rs;
        m_i = m_new;
        unsigned long long c2 = pk2(corr, corr);
#pragma unroll
        for (int i = 0; i < 8; i++) mul2(o2[i], c2);

        // O += P @ V, P exchanged via quad shuffles
#pragma unroll 1
        for (int gs = 0; gs < 4; gs++) {
            const int psrc = (lane & ~3) | gs;
#pragma unroll
            for (int jj = 0; jj < 16; jj++) {
                float pj = __shfl_sync(0xffffffffu, p[jj], psrc);
                unsigned long long p2 = pk2(pj, pj);
                const ulonglong2* vr4 =
                    (const ulonglong2*)&vs[(gs * 16 + jj) * 68 + d0];
                ulonglong2 va = vr4[0], vb2 = vr4[1];
                fma2(o2[0], p2, va.x);  fma2(o2[1], p2, va.y);
                fma2(o2[2], p2, vb2.x); fma2(o2[3], p2, vb2.y);
                ulonglong2 vc = vr4[2], vd = vr4[3];
                fma2(o2[4], p2, vc.x);  fma2(o2[5], p2, vc.y);
                fma2(o2[6], p2, vd.x);  fma2(o2[7], p2, vd.y);
            }
        }
    }

    float inv = 1.f / l_i;
    const int b = bh >> 4, h = bh & 15;
    float* dst = g_ctx + ((size_t)(b * kS + q0 + r)) * kE + h * kD + d0;
#pragma unroll
    for (int i = 0; i < 4; i++) {
        float2 x = up2(o2[2 * i]);
        float2 y = up2(o2[2 * i + 1]);
        *(float4*)(dst + 4 * i) = make_float4(x.x * inv, x.y * inv, y.x * inv, y.y * inv);
    }
}

extern "C" void kernel_launch(void* const* d_in, const int* in_sizes, int n_in,
                              void* d_out, int out_size) {
    const float* query = (const float*)d_in[0];
    // d_in[1] (key), d_in[2] (value) are unused by the reference computation
    const float* w_qkv = (const float*)d_in[3];
    const float* w_out = (const float*)d_in[4];
    float* out = (float*)d_out;

    gemm_qkv_kernel<<<dim3(32, 48), 256>>>(query, w_qkv);
    rope_kernel<<<8192, 256>>>();
    attn_kernel<<<dim3(32, 32), 256>>>();
    gemm_out_kernel<<<dim3(32, 16), 256>>>(w_out, out);
}

// round 2
// speedup vs baseline: 8.8097x; 8.8097x over previous
#include <cuda_runtime.h>
#include <math.h>

// Problem constants
#define kB 2
#define kS 2048
#define kE 1024
#define kH 16
#define kD 64
#define kBH (kB * kH)
#define kScale 0.125f

// Scratch (device globals: allocation-free)
static __device__ float g_q[kBH * kS * kD];    // [bh][s][d]
static __device__ float g_k[kBH * kS * kD];    // [bh][s][d]
static __device__ float g_vt[kBH * kD * kS];   // [bh][d][s]  (transposed V, tf32-rounded)
static __device__ float g_ctx[kB * kS * kE];   // [b][s][h*64+d]

// ---------------- tf32 helpers ----------------
__device__ __forceinline__ unsigned f2tf(float x) {
    unsigned u;
    asm("cvt.rna.tf32.f32 %0, %1;" : "=r"(u) : "f"(x));
    return u;
}
__device__ __forceinline__ float tf32r(float x) { return __uint_as_float(f2tf(x)); }
__device__ __forceinline__ unsigned fbits(float x) { return __float_as_uint(x); }

// D(16x8,f32) += A(16x8,tf32) * B(8x8,tf32)
__device__ __forceinline__ void mma8(float* c, const unsigned* a, const unsigned* b) {
    asm volatile(
        "mma.sync.aligned.m16n8k8.row.col.f32.tf32.tf32.f32 "
        "{%0,%1,%2,%3}, {%4,%5,%6,%7}, {%8,%9}, {%0,%1,%2,%3};"
        : "+f"(c[0]), "+f"(c[1]), "+f"(c[2]), "+f"(c[3])
        : "r"(a[0]), "r"(a[1]), "r"(a[2]), "r"(a[3]), "r"(b[0]), "r"(b[1]));
}

// ---------------- Tensor-core GEMM: out[m,n] = sum_k A[m,k] * W[n,k] ----------------
// BM=128, BN=64, BK=32. 256 threads = 8 warps (4m x 2n), warp tile 32x32.
// mode 0: A=query, W=w_qkv, scatter to g_q/g_k/g_vt.  mode 1: A=g_ctx, W=w_out -> out.
__global__ __launch_bounds__(256) void gemm_tc(const float* __restrict__ Ain,
                                               const float* __restrict__ W,
                                               float* __restrict__ out, int mode) {
    __shared__ float As[128][36];
    __shared__ float Ws[64][36];
    const float* A = (mode == 1) ? g_ctx : Ain;

    const int t = threadIdx.x;
    const int w = t >> 5, lane = t & 31;
    const int r = lane >> 2, q = lane & 3;
    const int wm = w >> 1, wn = w & 1;
    const int m0 = blockIdx.x * 128;
    const int n0g = blockIdx.y * 64;

    const int lrow = t >> 3;        // 0..31
    const int lcol = 4 * (t & 7);   // 0,4,...,28

    float c[2][4][4];
#pragma unroll
    for (int i = 0; i < 2; i++)
#pragma unroll
        for (int j = 0; j < 4; j++)
#pragma unroll
            for (int v = 0; v < 4; v++) c[i][j][v] = 0.f;

    float4 pa[4], pw[2];
#pragma unroll
    for (int i = 0; i < 4; i++)
        pa[i] = *(const float4*)(A + (size_t)(m0 + lrow + 32 * i) * kE + lcol);
#pragma unroll
    for (int i = 0; i < 2; i++)
        pw[i] = *(const float4*)(W + (size_t)(n0g + lrow + 32 * i) * kE + lcol);

    for (int k0 = 0; k0 < kE; k0 += 32) {
        __syncthreads();
#pragma unroll
        for (int i = 0; i < 4; i++) {
            float4 v = pa[i];
            *(float4*)&As[lrow + 32 * i][lcol] =
                make_float4(tf32r(v.x), tf32r(v.y), tf32r(v.z), tf32r(v.w));
        }
#pragma unroll
        for (int i = 0; i < 2; i++) {
            float4 v = pw[i];
            *(float4*)&Ws[lrow + 32 * i][lcol] =
                make_float4(tf32r(v.x), tf32r(v.y), tf32r(v.z), tf32r(v.w));
        }
        __syncthreads();
        if (k0 + 32 < kE) {
#pragma unroll
            for (int i = 0; i < 4; i++)
                pa[i] = *(const float4*)(A + (size_t)(m0 + lrow + 32 * i) * kE + k0 + 32 + lcol);
#pragma unroll
            for (int i = 0; i < 2; i++)
                pw[i] = *(const float4*)(W + (size_t)(n0g + lrow + 32 * i) * kE + k0 + 32 + lcol);
        }
#pragma unroll
        for (int kk = 0; kk < 4; kk++) {
            unsigned af[2][4], bf[4][2];
#pragma unroll
            for (int mt = 0; mt < 2; mt++) {
                int m = wm * 32 + mt * 16 + r;
                af[mt][0] = fbits(As[m][kk * 8 + q]);
                af[mt][1] = fbits(As[m + 8][kk * 8 + q]);
                af[mt][2] = fbits(As[m][kk * 8 + 4 + q]);
                af[mt][3] = fbits(As[m + 8][kk * 8 + 4 + q]);
            }
#pragma unroll
            for (int nt = 0; nt < 4; nt++) {
                int n = wn * 32 + nt * 8 + r;
                bf[nt][0] = fbits(Ws[n][kk * 8 + q]);
                bf[nt][1] = fbits(Ws[n][kk * 8 + 4 + q]);
            }
#pragma unroll
            for (int mt = 0; mt < 2; mt++)
#pragma unroll
                for (int nt = 0; nt < 4; nt++) mma8(c[mt][nt], af[mt], bf[nt]);
        }
    }

    // epilogue
    if (mode == 1) {
#pragma unroll
        for (int mt = 0; mt < 2; mt++)
#pragma unroll
            for (int nt = 0; nt < 4; nt++) {
                int mrow = m0 + wm * 32 + mt * 16 + r;
                int col = n0g + wn * 32 + nt * 8 + 2 * q;
                *(float2*)&out[(size_t)mrow * kE + col] =
                    make_float2(c[mt][nt][0], c[mt][nt][1]);
                *(float2*)&out[(size_t)(mrow + 8) * kE + col] =
                    make_float2(c[mt][nt][2], c[mt][nt][3]);
            }
    } else {
        const int by = blockIdx.y;
        const int which = by >> 4;   // 0=q 1=k 2=v
        const int h = by & 15;
#pragma unroll
        for (int mt = 0; mt < 2; mt++)
#pragma unroll
            for (int nt = 0; nt < 4; nt++) {
                int mrow = m0 + wm * 32 + mt * 16 + r;
                int dl = wn * 32 + nt * 8 + 2 * q;
                int b = mrow >> 11, s = mrow & (kS - 1);
                int bh = b * kH + h;
                if (which == 2) {
                    size_t base = ((size_t)(bh * kD + dl)) * kS;
                    g_vt[base + s] = tf32r(c[mt][nt][0]);
                    g_vt[base + kS + s] = tf32r(c[mt][nt][1]);
                    g_vt[base + s + 8] = tf32r(c[mt][nt][2]);
                    g_vt[base + kS + s + 8] = tf32r(c[mt][nt][3]);
                } else {
                    float* dst = (which == 0) ? g_q : g_k;
                    size_t base = ((size_t)(bh * kS + s)) * kD + dl;
                    *(float2*)&dst[base] = make_float2(c[mt][nt][0], c[mt][nt][1]);
                    *(float2*)&dst[base + 8 * kD] = make_float2(c[mt][nt][2], c[mt][nt][3]);
                }
            }
    }
}

// ---------------- RoPE (+ fold SCALE into q, round to tf32) ----------------
__global__ void rope_kernel() {
    int idx = blockIdx.x * 256 + threadIdx.x;  // 32*2048*32 threads
    int i = idx & 31;
    int s = (idx >> 5) & (kS - 1);
    int bh = idx >> 16;
    size_t base = ((size_t)bh * kS + s) * kD + 2 * i;
    float inv = expf(-(float)i * (9.210340371976184f / 32.0f));
    float freq = (float)s * inv;
    float sn, cs;
    sincosf(freq, &sn, &cs);
    float2 q2 = *(float2*)&g_q[base];
    float2 k2 = *(float2*)&g_k[base];
    float qr = (q2.x * cs - q2.y * sn) * kScale;
    float qi = (q2.x * sn + q2.y * cs) * kScale;
    *(float2*)&g_q[base] = make_float2(tf32r(qr), tf32r(qi));
    float kr = k2.x * cs - k2.y * sn;
    float ki = k2.x * sn + k2.y * cs;
    *(float2*)&g_k[base] = make_float2(tf32r(kr), tf32r(ki));
}

// ---------------- Flash attention with mma.sync tf32 ----------------
// grid: (32 q-tiles, 32 bh). block: 128 threads = 4 warps, warp = 16 q rows.
__global__ __launch_bounds__(128) void attn_tc() {
    __shared__ float Ks[64][68];  // [kv][d]
    __shared__ float Vs[64][68];  // [d][kv]
    const int t = threadIdx.x;
    const int w = t >> 5, lane = t & 31;
    const int r = lane >> 2, q = lane & 3;
    const int bh = blockIdx.y;
    const int q0 = blockIdx.x * 64;
    const float* qb = g_q + ((size_t)bh * kS + q0) * kD;
    const float* kb = g_k + (size_t)bh * kS * kD;
    const float* vtb = g_vt + (size_t)bh * kD * kS;

    // Stage Q tile (contiguous 16KB) into Ks, extract A-fragments
#pragma unroll
    for (int j = 0; j < 8; j++) {
        int f4i = t + 128 * j;
        *(float4*)&Ks[f4i >> 4][(f4i & 15) * 4] = ((const float4*)qb)[f4i];
    }
    __syncthreads();
    unsigned qa[8][4];
#pragma unroll
    for (int kk = 0; kk < 8; kk++) {
        int m = 16 * w + r;
        qa[kk][0] = fbits(Ks[m][kk * 8 + q]);
        qa[kk][1] = fbits(Ks[m + 8][kk * 8 + q]);
        qa[kk][2] = fbits(Ks[m][kk * 8 + 4 + q]);
        qa[kk][3] = fbits(Ks[m + 8][kk * 8 + 4 + q]);
    }

    float m0v = -1e30f, m1v = -1e30f, l0 = 0.f, l1 = 0.f;
    float o[8][4];
#pragma unroll
    for (int i = 0; i < 8; i++)
#pragma unroll
        for (int j = 0; j < 4; j++) o[i][j] = 0.f;

    const int src0 = (lane & ~3) | (q >> 1);
    const int src2 = src0 + 2;

    for (int kt = 0; kt < 32; kt++) {
        __syncthreads();
        {
            const float4* ksrc = (const float4*)(kb + (size_t)kt * 64 * kD);
#pragma unroll
            for (int j = 0; j < 8; j++) {
                int f4i = t + 128 * j;
                *(float4*)&Ks[f4i >> 4][(f4i & 15) * 4] = ksrc[f4i];
            }
#pragma unroll
            for (int j = 0; j < 8; j++) {
                int row = (t >> 4) + 8 * j;
                *(float4*)&Vs[row][4 * (t & 15)] =
                    ((const float4*)(vtb + (size_t)row * kS + kt * 64))[t & 15];
            }
        }
        __syncthreads();

        // S = Q K^T  (C frags: rows 16w+r, 16w+r+8; cols 8nt+2q, +1)
        float c[8][4];
#pragma unroll
        for (int i = 0; i < 8; i++)
#pragma unroll
            for (int j = 0; j < 4; j++) c[i][j] = 0.f;
#pragma unroll
        for (int kk = 0; kk < 8; kk++) {
#pragma unroll
            for (int nt = 0; nt < 8; nt++) {
                unsigned bf[2];
                bf[0] = fbits(Ks[8 * nt + r][kk * 8 + q]);
                bf[1] = fbits(Ks[8 * nt + r][kk * 8 + 4 + q]);
                mma8(c[nt], qa[kk], bf);
            }
        }

        // online softmax (rows r0 = 16w+r via c0,c1; r1 = +8 via c2,c3)
        float mt0 = -1e30f, mt1 = -1e30f;
#pragma unroll
        for (int nt = 0; nt < 8; nt++) {
            mt0 = fmaxf(mt0, fmaxf(c[nt][0], c[nt][1]));
            mt1 = fmaxf(mt1, fmaxf(c[nt][2], c[nt][3]));
        }
        mt0 = fmaxf(mt0, __shfl_xor_sync(0xffffffffu, mt0, 1));
        mt0 = fmaxf(mt0, __shfl_xor_sync(0xffffffffu, mt0, 2));
        mt1 = fmaxf(mt1, __shfl_xor_sync(0xffffffffu, mt1, 1));
        mt1 = fmaxf(mt1, __shfl_xor_sync(0xffffffffu, mt1, 2));
        float mn0 = fmaxf(m0v, mt0), mn1 = fmaxf(m1v, mt1);
        float cor0 = __expf(m0v - mn0), cor1 = __expf(m1v - mn1);
        m0v = mn0; m1v = mn1;
        float rs0 = 0.f, rs1 = 0.f;
#pragma unroll
        for (int nt = 0; nt < 8; nt++) {
            c[nt][0] = __expf(c[nt][0] - mn0); rs0 += c[nt][0];
            c[nt][1] = __expf(c[nt][1] - mn0); rs0 += c[nt][1];
            c[nt][2] = __expf(c[nt][2] - mn1); rs1 += c[nt][2];
            c[nt][3] = __expf(c[nt][3] - mn1); rs1 += c[nt][3];
        }
        rs0 += __shfl_xor_sync(0xffffffffu, rs0, 1);
        rs0 += __shfl_xor_sync(0xffffffffu, rs0, 2);
        rs1 += __shfl_xor_sync(0xffffffffu, rs1, 1);
        rs1 += __shfl_xor_sync(0xffffffffu, rs1, 2);
        l0 = l0 * cor0 + rs0;
        l1 = l1 * cor1 + rs1;
#pragma unroll
        for (int nt = 0; nt < 8; nt++) {
            o[nt][0] *= cor0; o[nt][1] *= cor0;
            o[nt][2] *= cor1; o[nt][3] *= cor1;
        }

        // O += P V  (A-frags of P built via intra-quad shuffles of C frags)
#pragma unroll
        for (int kk = 0; kk < 8; kk++) {
            float u0 = __shfl_sync(0xffffffffu, c[kk][0], src0);
            float u1 = __shfl_sync(0xffffffffu, c[kk][1], src0);
            float u2 = __shfl_sync(0xffffffffu, c[kk][2], src0);
            float u3 = __shfl_sync(0xffffffffu, c[kk][3], src0);
            float v0 = __shfl_sync(0xffffffffu, c[kk][0], src2);
            float v1 = __shfl_sync(0xffffffffu, c[kk][1], src2);
            float v2 = __shfl_sync(0xffffffffu, c[kk][2], src2);
            float v3 = __shfl_sync(0xffffffffu, c[kk][3], src2);
            unsigned pa[4];
            pa[0] = f2tf((q & 1) ? u1 : u0);
            pa[1] = f2tf((q & 1) ? u3 : u2);
            pa[2] = f2tf((q & 1) ? v1 : v0);
            pa[3] = f2tf((q & 1) ? v3 : v2);
#pragma unroll
            for (int nt = 0; nt < 8; nt++) {
                unsigned bf[2];
                bf[0] = fbits(Vs[8 * nt + r][kk * 8 + q]);
                bf[1] = fbits(Vs[8 * nt + r][kk * 8 + 4 + q]);
                mma8(o[nt], pa, bf);
            }
        }
    }

    // epilogue: normalize and store to ctx [b][s][h*64+d]
    float il0 = 1.f / l0, il1 = 1.f / l1;
    const int b = bh >> 4, h = bh & 15;
    const int row0 = q0 + 16 * w + r;
    float* dst = g_ctx + ((size_t)(b * kS + row0)) * kE + h * kD;
#pragma unroll
    for (int nt = 0; nt < 8; nt++) {
        *(float2*)&dst[8 * nt + 2 * q] =
            make_float2(o[nt][0] * il0, o[nt][1] * il0);
        *(float2*)&dst[8 * kE + 8 * nt + 2 * q] =
            make_float2(o[nt][2] * il1, o[nt][3] * il1);
    }
}

extern "C" void kernel_launch(void* const* d_in, const int* in_sizes, int n_in,
                              void* d_out, int out_size) {
    const float* query = (const float*)d_in[0];
    // d_in[1] (key), d_in[2] (value) are unused by the reference computation
    const float* w_qkv = (const float*)d_in[3];
    const float* w_out = (const float*)d_in[4];
    float* out = (float*)d_out;

    gemm_tc<<<dim3(32, 48), 256>>>(query, w_qkv, nullptr, 0);
    rope_kernel<<<8192, 256>>>();
    attn_tc<<<dim3(32, 32), 128>>>();
    gemm_tc<<<dim3(32, 16), 256>>>(nullptr, w_out, out, 1);
}

// round 3
// speedup vs baseline: 8.9636x; 1.0175x over previous
#include <cuda_runtime.h>
#include <math.h>

// Problem constants
#define kB 2
#define kS 2048
#define kE 1024
#define kH 16
#define kD 64
#define kBH (kB * kH)
#define kScale 0.125f
#define kLN1e4 9.210340371976184f

// Scratch (device globals: allocation-free)
static __device__ float g_q[kBH * kS * kD];    // [bh][s][d]  (tf32, rope+scale applied)
static __device__ float g_k[kBH * kS * kD];    // [bh][s][d]  (tf32, rope applied)
static __device__ float g_vt[kBH * kD * kS];   // [bh][d][s]  (tf32, transposed V)
static __device__ float g_ctx[kB * kS * kE];   // [b][s][h*64+d]

// ---------------- helpers ----------------
__device__ __forceinline__ unsigned f2tf(float x) {
    unsigned u;
    asm("cvt.rna.tf32.f32 %0, %1;" : "=r"(u) : "f"(x));
    return u;
}
__device__ __forceinline__ float tf32r(float x) { return __uint_as_float(f2tf(x)); }

__device__ __forceinline__ unsigned smem_u32(const void* p) {
    unsigned r;
    asm("{ .reg .u64 t; cvta.to.shared.u64 t, %1; cvt.u32.u64 %0, t; }"
        : "=r"(r) : "l"(p));
    return r;
}
__device__ __forceinline__ void ldsm4(unsigned* f, unsigned addr) {
    asm volatile("ldmatrix.sync.aligned.m8n8.x4.shared.b16 {%0,%1,%2,%3}, [%4];"
                 : "=r"(f[0]), "=r"(f[1]), "=r"(f[2]), "=r"(f[3]) : "r"(addr));
}
// D(16x8,f32) += A(16x8,tf32) * B(8x8,tf32)
__device__ __forceinline__ void mma8(float* c, const unsigned* a, const unsigned* b) {
    asm volatile(
        "mma.sync.aligned.m16n8k8.row.col.f32.tf32.tf32.f32 "
        "{%0,%1,%2,%3}, {%4,%5,%6,%7}, {%8,%9}, {%0,%1,%2,%3};"
        : "+f"(c[0]), "+f"(c[1]), "+f"(c[2]), "+f"(c[3])
        : "r"(a[0]), "r"(a[1]), "r"(a[2]), "r"(a[3]), "r"(b[0]), "r"(b[1]));
}

// ---------------- Tensor-core GEMM: out[m,n] = sum_k A[m,k]*W[n,k] ----------------
// BM=128, BN=128, BK=16, double-buffered. 256 threads = 8 warps (2m x 4n),
// warp tile 64x32.  mode 0: A=query, W=w_qkv -> g_q/g_k/g_vt (RoPE fused).
// mode 1: A=g_ctx, W=w_out -> out.
#define GBK 16
#define GPAD 20
__global__ __launch_bounds__(256) void gemm_tc(const float* __restrict__ Ain,
                                               const float* __restrict__ W,
                                               float* __restrict__ out, int mode) {
    __shared__ float As[2][128][GPAD];
    __shared__ float Ws[2][128][GPAD];
    const float* A = (mode == 1) ? g_ctx : Ain;

    const int t = threadIdx.x;
    const int w = t >> 5, lane = t & 31;
    const int r = lane >> 2, q = lane & 3;
    const int wm = w >> 2, wn = w & 3;
    const int m0 = blockIdx.x * 128;
    const int n0 = blockIdx.y * 128;

    const int lrow = t >> 2;        // 0..63
    const int lcol = 4 * (t & 3);   // 0,4,8,12

    float c[4][4][4];
#pragma unroll
    for (int i = 0; i < 4; i++)
#pragma unroll
        for (int j = 0; j < 4; j++)
#pragma unroll
            for (int v = 0; v < 4; v++) c[i][j][v] = 0.f;

    const float* Arow0 = A + (size_t)(m0 + lrow) * kE + lcol;
    const float* Arow1 = A + (size_t)(m0 + lrow + 64) * kE + lcol;
    const float* Wrow0 = W + (size_t)(n0 + lrow) * kE + lcol;
    const float* Wrow1 = W + (size_t)(n0 + lrow + 64) * kE + lcol;

    float4 pa0 = *(const float4*)Arow0;
    float4 pa1 = *(const float4*)Arow1;
    float4 pw0 = *(const float4*)Wrow0;
    float4 pw1 = *(const float4*)Wrow1;

    // stage 0 store
    *(float4*)&As[0][lrow][lcol] =
        make_float4(tf32r(pa0.x), tf32r(pa0.y), tf32r(pa0.z), tf32r(pa0.w));
    *(float4*)&As[0][lrow + 64][lcol] =
        make_float4(tf32r(pa1.x), tf32r(pa1.y), tf32r(pa1.z), tf32r(pa1.w));
    *(float4*)&Ws[0][lrow][lcol] =
        make_float4(tf32r(pw0.x), tf32r(pw0.y), tf32r(pw0.z), tf32r(pw0.w));
    *(float4*)&Ws[0][lrow + 64][lcol] =
        make_float4(tf32r(pw1.x), tf32r(pw1.y), tf32r(pw1.z), tf32r(pw1.w));
    __syncthreads();

    // ldmatrix per-lane base addresses (stage 0)
    const unsigned aBase = smem_u32(&As[0][0][0]);
    const unsigned wBase = smem_u32(&Ws[0][0][0]);
    const unsigned stageSz = 128 * GPAD * 4;
    unsigned aoff[4], woff[2];
#pragma unroll
    for (int mt = 0; mt < 4; mt++)
        aoff[mt] = aBase +
                   ((wm * 64 + mt * 16 + (lane & 15)) * GPAD + (lane >> 4) * 4) * 4;
#pragma unroll
    for (int ng = 0; ng < 2; ng++)
        woff[ng] = wBase + ((wn * 32 + ng * 16 + (lane & 7) + ((lane >> 4) & 1) * 8) *
                                GPAD +
                            ((lane >> 3) & 1) * 4) *
                               4;

    const int NIT = kE / GBK;  // 64
    for (int it = 0; it < NIT; it++) {
        const int cur = it & 1;
        if (it + 1 < NIT) {
            int k0 = (it + 1) * GBK;
            pa0 = *(const float4*)(Arow0 + k0);
            pa1 = *(const float4*)(Arow1 + k0);
            pw0 = *(const float4*)(Wrow0 + k0);
            pw1 = *(const float4*)(Wrow1 + k0);
        }
        const unsigned aS = cur ? stageSz : 0u;
        const unsigned wS = cur ? stageSz : 0u;
#pragma unroll
        for (int kk = 0; kk < 2; kk++) {
            unsigned af[4][4], bf[2][4];
#pragma unroll
            for (int mt = 0; mt < 4; mt++) ldsm4(af[mt], aoff[mt] + aS + kk * 32);
#pragma unroll
            for (int ng = 0; ng < 2; ng++) ldsm4(bf[ng], woff[ng] + wS + kk * 32);
#pragma unroll
            for (int mt = 0; mt < 4; mt++)
#pragma unroll
                for (int ng = 0; ng < 2; ng++) {
                    mma8(c[mt][2 * ng], af[mt], &bf[ng][0]);
                    mma8(c[mt][2 * ng + 1], af[mt], &bf[ng][2]);
                }
        }
        if (it + 1 < NIT) {
            const int nxt = cur ^ 1;
            *(float4*)&As[nxt][lrow][lcol] =
                make_float4(tf32r(pa0.x), tf32r(pa0.y), tf32r(pa0.z), tf32r(pa0.w));
            *(float4*)&As[nxt][lrow + 64][lcol] =
                make_float4(tf32r(pa1.x), tf32r(pa1.y), tf32r(pa1.z), tf32r(pa1.w));
            *(float4*)&Ws[nxt][lrow][lcol] =
                make_float4(tf32r(pw0.x), tf32r(pw0.y), tf32r(pw0.z), tf32r(pw0.w));
            *(float4*)&Ws[nxt][lrow + 64][lcol] =
                make_float4(tf32r(pw1.x), tf32r(pw1.y), tf32r(pw1.z), tf32r(pw1.w));
        }
        __syncthreads();
    }

    // ---------------- epilogue ----------------
    if (mode == 1) {
#pragma unroll
        for (int mt = 0; mt < 4; mt++)
#pragma unroll
            for (int nt = 0; nt < 4; nt++) {
                int mrow = m0 + wm * 64 + mt * 16 + r;
                int col = n0 + wn * 32 + (nt >> 1) * 16 + (nt & 1) * 8 + 2 * q;
                *(float2*)&out[(size_t)mrow * kE + col] =
                    make_float2(c[mt][nt][0], c[mt][nt][1]);
                *(float2*)&out[(size_t)(mrow + 8) * kE + col] =
                    make_float2(c[mt][nt][2], c[mt][nt][3]);
            }
    } else {
        const int which = (n0 >> 10);  // 0=q 1=k 2=v
#pragma unroll
        for (int mt = 0; mt < 4; mt++)
#pragma unroll
            for (int nt = 0; nt < 4; nt++) {
                int mrow = m0 + wm * 64 + mt * 16 + r;
                int n = n0 + wn * 32 + (nt >> 1) * 16 + (nt & 1) * 8 + 2 * q;
                int h = (n >> 6) & 15;
                int dl = n & 63;
                int b = mrow >> 11, s = mrow & (kS - 1);
                int bh = b * kH + h;
                if (which == 2) {
                    size_t base = ((size_t)(bh * kD + dl)) * kS;
                    g_vt[base + s] = tf32r(c[mt][nt][0]);
                    g_vt[base + kS + s] = tf32r(c[mt][nt][1]);
                    g_vt[base + s + 8] = tf32r(c[mt][nt][2]);
                    g_vt[base + kS + s + 8] = tf32r(c[mt][nt][3]);
                } else {
                    // fused RoPE: (dl, dl+1) is the rotation pair, i = dl/2
                    int i = dl >> 1;
                    float inv = expf(-(float)i * (kLN1e4 / 32.0f));
                    float sn0, cs0, sn1, cs1;
                    sincosf((float)s * inv, &sn0, &cs0);
                    sincosf((float)(s + 8) * inv, &sn1, &cs1);
                    float y0 = c[mt][nt][0] * cs0 - c[mt][nt][1] * sn0;
                    float y1 = c[mt][nt][0] * sn0 + c[mt][nt][1] * cs0;
                    float z0 = c[mt][nt][2] * cs1 - c[mt][nt][3] * sn1;
                    float z1 = c[mt][nt][2] * sn1 + c[mt][nt][3] * cs1;
                    float* dst;
                    if (which == 0) {
                        y0 *= kScale; y1 *= kScale; z0 *= kScale; z1 *= kScale;
                        dst = g_q;
                    } else {
                        dst = g_k;
                    }
                    size_t base = ((size_t)(bh * kS + s)) * kD + dl;
                    *(float2*)&dst[base] = make_float2(tf32r(y0), tf32r(y1));
                    *(float2*)&dst[base + 8 * kD] = make_float2(tf32r(z0), tf32r(z1));
                }
            }
    }
}

// ---------------- Flash attention with mma.sync tf32 + ldmatrix ----------------
// grid: (32 q-tiles, 32 bh). block: 128 threads = 4 warps, warp = 16 q rows.
__global__ __launch_bounds__(128) void attn_tc() {
    __shared__ float Ks[64][68];  // [kv][d]
    __shared__ float Vs[64][68];  // [d][kv]
    const int t = threadIdx.x;
    const int w = t >> 5, lane = t & 31;
    const int r = lane >> 2, q = lane & 3;
    const int bh = blockIdx.y;
    const int q0 = blockIdx.x * 64;
    const float* qb = g_q + ((size_t)bh * kS + q0) * kD;
    const float* kb = g_k + (size_t)bh * kS * kD;
    const float* vtb = g_vt + (size_t)bh * kD * kS;

    // Stage Q tile into Ks, extract A-fragments via ldmatrix
#pragma unroll
    for (int j = 0; j < 8; j++) {
        int f4i = t + 128 * j;
        *(float4*)&Ks[f4i >> 4][(f4i & 15) * 4] = ((const float4*)qb)[f4i];
    }
    __syncthreads();
    const unsigned kA = smem_u32(&Ks[0][0]);
    const unsigned vA = smem_u32(&Vs[0][0]);
    unsigned qa[8][4];
    {
        unsigned qaddr = kA + ((16 * w + (lane & 15)) * 68 + (lane >> 4) * 4) * 4;
#pragma unroll
        for (int kk = 0; kk < 8; kk++) ldsm4(qa[kk], qaddr + kk * 32);
    }
    const unsigned boff =
        (((lane & 7) + ((lane >> 4) & 1) * 8) * 68 + ((lane >> 3) & 1) * 4) * 4;

    float m0v = -1e30f, m1v = -1e30f, l0 = 0.f, l1 = 0.f;
    float o[8][4];
#pragma unroll
    for (int i = 0; i < 8; i++)
#pragma unroll
        for (int j = 0; j < 4; j++) o[i][j] = 0.f;

    const int src0 = (lane & ~3) | (q >> 1);
    const int src2 = src0 + 2;

    for (int kt = 0; kt < 32; kt++) {
        __syncthreads();
        {
            const float4* ksrc = (const float4*)(kb + (size_t)kt * 64 * kD);
#pragma unroll
            for (int j = 0; j < 8; j++) {
                int f4i = t + 128 * j;
                *(float4*)&Ks[f4i >> 4][(f4i & 15) * 4] = ksrc[f4i];
            }
#pragma unroll
            for (int j = 0; j < 8; j++) {
                int row = (t >> 4) + 8 * j;
                *(float4*)&Vs[row][4 * (t & 15)] =
                    ((const float4*)(vtb + (size_t)row * kS + kt * 64))[t & 15];
            }
        }
        __syncthreads();

        // S = Q K^T  (c[2ng+h] covers cols 16ng + 8h + {2q,2q+1})
        float c[8][4];
#pragma unroll
        for (int i = 0; i < 8; i++)
#pragma unroll
            for (int j = 0; j < 4; j++) c[i][j] = 0.f;
#pragma unroll
        for (int kk = 0; kk < 8; kk++) {
#pragma unroll
            for (int ng = 0; ng < 4; ng++) {
                unsigned bf[4];
                ldsm4(bf, kA + boff + ng * (16 * 68 * 4) + kk * 32);
                mma8(c[2 * ng], qa[kk], &bf[0]);
                mma8(c[2 * ng + 1], qa[kk], &bf[2]);
            }
        }

        // online softmax (rows r0 = 16w+r via c0,c1; r1 = +8 via c2,c3)
        float mt0 = -1e30f, mt1 = -1e30f;
#pragma unroll
        for (int nt = 0; nt < 8; nt++) {
            mt0 = fmaxf(mt0, fmaxf(c[nt][0], c[nt][1]));
            mt1 = fmaxf(mt1, fmaxf(c[nt][2], c[nt][3]));
        }
        mt0 = fmaxf(mt0, __shfl_xor_sync(0xffffffffu, mt0, 1));
        mt0 = fmaxf(mt0, __shfl_xor_sync(0xffffffffu, mt0, 2));
        mt1 = fmaxf(mt1, __shfl_xor_sync(0xffffffffu, mt1, 1));
        mt1 = fmaxf(mt1, __shfl_xor_sync(0xffffffffu, mt1, 2));
        float mn0 = fmaxf(m0v, mt0), mn1 = fmaxf(m1v, mt1);
        float cor0 = __expf(m0v - mn0), cor1 = __expf(m1v - mn1);
        m0v = mn0; m1v = mn1;
        float rs0 = 0.f, rs1 = 0.f;
#pragma unroll
        for (int nt = 0; nt < 8; nt++) {
            c[nt][0] = __expf(c[nt][0] - mn0); rs0 += c[nt][0];
            c[nt][1] = __expf(c[nt][1] - mn0); rs0 += c[nt][1];
            c[nt][2] = __expf(c[nt][2] - mn1); rs1 += c[nt][2];
            c[nt][3] = __expf(c[nt][3] - mn1); rs1 += c[nt][3];
        }
        rs0 += __shfl_xor_sync(0xffffffffu, rs0, 1);
        rs0 += __shfl_xor_sync(0xffffffffu, rs0, 2);
        rs1 += __shfl_xor_sync(0xffffffffu, rs1, 1);
        rs1 += __shfl_xor_sync(0xffffffffu, rs1, 2);
        l0 = l0 * cor0 + rs0;
        l1 = l1 * cor1 + rs1;
#pragma unroll
        for (int nt = 0; nt < 8; nt++) {
            o[nt][0] *= cor0; o[nt][1] *= cor0;
            o[nt][2] *= cor1; o[nt][3] *= cor1;
        }

        // O += P V  (A-frags of P via intra-quad shuffles; kv-chunk kk comes
        // from score col group: c[2*(kk>>1) + ((kk&1))] -> cols 16*(kk>>1)+8*(kk&1))
#pragma unroll
        for (int kk = 0; kk < 8; kk++) {
            // scores for kv columns kk*8 .. kk*8+7 live in c[idx]
            const int idx = kk;  // col(c[idx]) = 16*(idx>>1)+8*(idx&1) = 8*kk  ✓
            float u0 = __shfl_sync(0xffffffffu, c[idx][0], src0);
            float u1 = __shfl_sync(0xffffffffu, c[idx][1], src0);
            float u2 = __shfl_sync(0xffffffffu, c[idx][2], src0);
            float u3 = __shfl_sync(0xffffffffu, c[idx][3], src0);
            float v0 = __shfl_sync(0xffffffffu, c[idx][0], src2);
            float v1 = __shfl_sync(0xffffffffu, c[idx][1], src2);
            float v2 = __shfl_sync(0xffffffffu, c[idx][2], src2);
            float v3 = __shfl_sync(0xffffffffu, c[idx][3], src2);
            unsigned pa[4];
            pa[0] = f2tf((q & 1) ? u1 : u0);
            pa[1] = f2tf((q & 1) ? u3 : u2);
            pa[2] = f2tf((q & 1) ? v1 : v0);
            pa[3] = f2tf((q & 1) ? v3 : v2);
#pragma unroll
            for (int ng = 0; ng < 4; ng++) {
                unsigned bf[4];
                ldsm4(bf, vA + boff + ng * (16 * 68 * 4) + kk * 32);
                mma8(o[2 * ng], pa, &bf[0]);
                mma8(o[2 * ng + 1], pa, &bf[2]);
            }
        }
    }

    // epilogue: normalize and store to ctx [b][s][h*64+d]
    float il0 = 1.f / l0, il1 = 1.f / l1;
    const int b = bh >> 4, h = bh & 15;
    const int row0 = q0 + 16 * w + r;
    float* dst = g_ctx + ((size_t)(b * kS + row0)) * kE + h * kD;
#pragma unroll
    for (int nt = 0; nt < 8; nt++) {
        int col = 16 * (nt >> 1) + 8 * (nt & 1) + 2 * q;
        *(float2*)&dst[col] = make_float2(o[nt][0] * il0, o[nt][1] * il0);
        *(float2*)&dst[8 * kE + col] = make_float2(o[nt][2] * il1, o[nt][3] * il1);
    }
}

extern "C" void kernel_launch(void* const* d_in, const int* in_sizes, int n_in,
                              void* d_out, int out_size) {
    const float* query = (const float*)d_in[0];
    // d_in[1] (key), d_in[2] (value) are unused by the reference computation
    const float* w_qkv = (const float*)d_in[3];
    const float* w_out = (const float*)d_in[4];
    float* out = (float*)d_out;

    gemm_tc<<<dim3(32, 24), 256>>>(query, w_qkv, nullptr, 0);
    attn_tc<<<dim3(32, 32), 128>>>();
    gemm_tc<<<dim3(32, 8), 256>>>(nullptr, w_out, out, 1);
}